// round 12
// baseline (speedup 1.0000x reference)
#include <cuda_runtime.h>

#define B_      32
#define DIM_    4096
#define NH_     32
#define NKV_    8
#define HD_     128
#define NREP_   4
#define T_TOT   2048
#define START_  2047
#define QKV_N   6144
#define SK_     8
#define TILE_N  128
#define TILE_K  32
#define SPLITS_ 2
#define TOK_PER_SPLIT 1024
#define TOK_PER_WARP  256
#define NPART_  8    // SPLITS_ * 4 warps
#define KT_ROWS 8           // K subtile rows per warp
#define KT_PITCH 132        // floats per row (528B -> conflict-free)

typedef unsigned long long ull;

// ---------------- scratch (device globals; no runtime allocation) ----------
__device__ float g_part[SK_ * B_ * QKV_N];
__device__ float g_qkv [B_ * QKV_N];
__device__ float g_attn[B_ * NH_ * HD_];
__device__ float g_pm  [B_ * NH_ * NPART_];
__device__ float g_pl  [B_ * NH_ * NPART_];
__device__ float g_po  [(size_t)B_ * NH_ * NPART_ * HD_];

// packed fp32x2 FMA (GEMM only; measured win there)
__device__ __forceinline__ void ffma2(ull& d, ull a, ull b)
{
    asm("fma.rn.f32x2 %0, %1, %2, %0;" : "+l"(d) : "l"(a), "l"(b));
}

// ---------------- split-K tall-skinny GEMM with K-pair FFMA2 ---------------
__device__ __forceinline__ void gemm_body(const float* __restrict__ A,
                                          const float* __restrict__ W,
                                          int N, int col0, int n0, int ky)
{
    __shared__ float xs[B_][TILE_K + 2];
    __shared__ float ws[TILE_N][TILE_K + 2];

    const int kbeg = ky * (DIM_ / SK_);       // 512 per split
    const int tid  = threadIdx.x;
    const int tx   = tid & 15;
    const int ty   = tid >> 4;

    ull acc[4][8];
#pragma unroll
    for (int i = 0; i < 4; i++)
#pragma unroll
        for (int j = 0; j < 8; j++) acc[i][j] = 0ull;

    for (int kt = 0; kt < DIM_ / SK_; kt += TILE_K) {
        const int k0 = kbeg + kt;
#pragma unroll
        for (int it = 0; it < (TILE_K * TILE_N) / 128; it++) {
            int idx = tid + it * 128;
            int kk = idx >> 7;
            int nn = idx & 127;
            ws[nn][kk] = W[(size_t)(k0 + kk) * N + n0 + nn];
        }
#pragma unroll
        for (int it = 0; it < (B_ * TILE_K) / 128; it++) {
            int idx = tid + it * 128;
            int bb = idx >> 5;
            int kk = idx & 31;
            xs[bb][kk] = A[(size_t)bb * DIM_ + k0 + kk];
        }
        __syncthreads();
#pragma unroll
        for (int kp = 0; kp < TILE_K / 2; kp++) {
            ull xv[4], wv[8];
#pragma unroll
            for (int i = 0; i < 4; i++)
                xv[i] = *reinterpret_cast<const ull*>(&xs[ty + 8 * i][2 * kp]);
#pragma unroll
            for (int j = 0; j < 8; j++)
                wv[j] = *reinterpret_cast<const ull*>(&ws[tx + 16 * j][2 * kp]);
#pragma unroll
            for (int i = 0; i < 4; i++)
#pragma unroll
                for (int j = 0; j < 8; j++)
                    ffma2(acc[i][j], xv[i], wv[j]);
        }
        __syncthreads();
    }
#pragma unroll
    for (int i = 0; i < 4; i++) {
        int bb = ty + 8 * i;
#pragma unroll
        for (int j = 0; j < 8; j++) {
            float2 v = *reinterpret_cast<const float2*>(&acc[i][j]);
            int nn = col0 + n0 + tx + 16 * j;
            g_part[((size_t)ky * B_ + bb) * QKV_N + nn] = v.x + v.y;
        }
    }
}

__global__ void __launch_bounds__(128)
gemm_qkv(const float* __restrict__ x, const float* __restrict__ wq,
         const float* __restrict__ wk, const float* __restrict__ wv)
{
    const int tile = blockIdx.x;
    const int ky   = blockIdx.y;
    if (tile < 32)       gemm_body(x, wq, 4096, 0,    tile * TILE_N,        ky);
    else if (tile < 40)  gemm_body(x, wk, 1024, 4096, (tile - 32) * TILE_N, ky);
    else                 gemm_body(x, wv, 1024, 5120, (tile - 40) * TILE_N, ky);
}

__global__ void __launch_bounds__(128)
gemm_o(const float* __restrict__ W)
{
    gemm_body(g_attn, W, 4096, 0, blockIdx.x * TILE_N, blockIdx.y);
}

// ---------------- fused reduce + RoPE (float2 pairs) -----------------------
__global__ void reduce_rope(const float* __restrict__ fc, const float* __restrict__ fs)
{
    const int idx = blockIdx.x * blockDim.x + threadIdx.x;
    const int b2  = idx / 3072;
    const int cp  = idx - b2 * 3072;
    float2 s = make_float2(0.f, 0.f);
#pragma unroll
    for (int ky = 0; ky < SK_; ky++) {
        float2 v = reinterpret_cast<const float2*>(g_part)[(size_t)(ky * B_ + b2) * 3072 + cp];
        s.x += v.x; s.y += v.y;
    }
    if (cp < 2560) {
        int f = cp & 63;
        float c = fc[f], sn = fs[f];
        float xr = s.x, xi = s.y;
        s.x = xr * c - xi * sn;
        s.y = xr * sn + xi * c;
    }
    reinterpret_cast<float2*>(g_qkv)[(size_t)b2 * 3072 + cp] = s;
}

__global__ void reduce_wo(float* __restrict__ out)
{
    const int i = blockIdx.x * blockDim.x + threadIdx.x;
    const int b2 = i >> 10;
    const int nn = i & 1023;
    float4 s = make_float4(0.f, 0.f, 0.f, 0.f);
#pragma unroll
    for (int ky = 0; ky < SK_; ky++) {
        float4 v = reinterpret_cast<const float4*>(g_part)[(size_t)(ky * B_ + b2) * (QKV_N / 4) + nn];
        s.x += v.x; s.y += v.y; s.z += v.z; s.w += v.w;
    }
    reinterpret_cast<float4*>(out)[(size_t)b2 * 1024 + nn] = s;
}

// ---------------- flash-decode attention ----------------------------------
// grid: b(32)*g(8)*split(2) = 512 blocks, 128 threads. ~19KB smem ->
// >=6 CTAs/SM -> 888 slots >= 512 -> single wave with margin.
__global__ void __launch_bounds__(128)
attn_kernel(const float* __restrict__ kc, const float* __restrict__ vc)
{
    const int blk = blockIdx.x;
    const int sp  = blk & 1;
    const int g   = (blk >> 1) & 7;
    const int bb  = blk >> 4;
    const int tid = threadIdx.x;
    const int w   = tid >> 5;
    const int lane = tid & 31;

    __shared__ float q_s[NREP_][HD_];
    __shared__ float ktile[4][KT_ROWS][KT_PITCH];   // per-warp K subtile

    for (int idx = tid; idx < NREP_ * HD_; idx += 128) {
        int h = idx >> 7, d = idx & 127;
        q_s[h][d] = g_qkv[bb * QKV_N + (g * NREP_ + h) * HD_ + d];
    }
    __syncthreads();

    const float scale = 0.08838834764831845f;   // 1/sqrt(128)
    float m[4], l[4], acc[4][4];
#pragma unroll
    for (int h = 0; h < 4; h++) {
        m[h] = -1e30f; l[h] = 0.f;
#pragma unroll
        for (int j = 0; j < 4; j++) acc[h][j] = 0.f;
    }

    const int tbase = sp * TOK_PER_SPLIT + w * TOK_PER_WARP;
    const float* knew = &g_qkv[bb * QKV_N + 4096 + g * HD_];
    const float* vnew = &g_qkv[bb * QKV_N + 5120 + g * HD_];

    const int tkn = lane & 7;      // token within 8-row subtile
    const int q4i = lane >> 3;     // dim quarter (32 dims each)

    for (int r = 0; r < TOK_PER_WARP / KT_ROWS; r++) {       // 32 subtiles of 8
        const int tb = tbase + r * KT_ROWS;

        // ---- coalesced K fill: one 512B row per iteration ----
#pragma unroll
        for (int rr = 0; rr < KT_ROWS; rr++) {
            const int t = tb + rr;
            const float* krow = (t == START_)
                ? knew
                : kc + (((size_t)bb * T_TOT + t) * NKV_ + g) * HD_;
            float4 kv = __ldg(reinterpret_cast<const float4*>(krow) + lane);
            *reinterpret_cast<float4*>(&ktile[w][rr][lane * 4]) = kv;
        }
        __syncwarp();

        // ---- scores: 4 lanes per token, 32 dims each ----
        float s4[4] = {0.f, 0.f, 0.f, 0.f};
#pragma unroll
        for (int i = 0; i < 8; i++) {
            float4 k4 = *reinterpret_cast<const float4*>(&ktile[w][tkn][q4i * 32 + i * 4]);
#pragma unroll
            for (int h = 0; h < 4; h++) {
                float4 q4 = *(reinterpret_cast<const float4*>(&q_s[h][q4i * 32]) + i);
                s4[h] += k4.x * q4.x + k4.y * q4.y + k4.z * q4.z + k4.w * q4.w;
            }
        }
        __syncwarp();

        float p[4];
#pragma unroll
        for (int h = 0; h < 4; h++) {
            float sc = s4[h];
            sc += __shfl_xor_sync(0xffffffffu, sc, 8);
            sc += __shfl_xor_sync(0xffffffffu, sc, 16);
            sc *= scale;
            float mx = sc;
#pragma unroll
            for (int o = 4; o > 0; o >>= 1)
                mx = fmaxf(mx, __shfl_xor_sync(0xffffffffu, mx, o));
            float mnew = fmaxf(m[h], mx);
            float corr = __expf(m[h] - mnew);
            p[h] = __expf(sc - mnew);
            float ps = p[h];
#pragma unroll
            for (int o = 4; o > 0; o >>= 1)
                ps += __shfl_xor_sync(0xffffffffu, ps, o);
            l[h] = l[h] * corr + ps;
            m[h] = mnew;
#pragma unroll
            for (int j = 0; j < 4; j++) acc[h][j] *= corr;
        }

        // ---- V accumulation (coalesced, batched 8 for MLP) ----
        {
            float4 v8[KT_ROWS];
#pragma unroll
            for (int u = 0; u < KT_ROWS; u++) {
                const int t2 = tb + u;
                const float* vrow = (t2 == START_)
                    ? vnew
                    : vc + (((size_t)bb * T_TOT + t2) * NKV_ + g) * HD_;
                v8[u] = __ldg(reinterpret_cast<const float4*>(vrow) + lane);
            }
#pragma unroll
            for (int u = 0; u < KT_ROWS; u++) {
                float pt[4];
#pragma unroll
                for (int h = 0; h < 4; h++)
                    pt[h] = __shfl_sync(0xffffffffu, p[h], u);
#pragma unroll
                for (int h = 0; h < 4; h++) {
                    acc[h][0] += pt[h] * v8[u].x;
                    acc[h][1] += pt[h] * v8[u].y;
                    acc[h][2] += pt[h] * v8[u].z;
                    acc[h][3] += pt[h] * v8[u].w;
                }
            }
        }
    }

    const int sp8 = sp * 4 + w;          // 0..7 partial slots
#pragma unroll
    for (int h = 0; h < 4; h++) {
        const int hh = g * NREP_ + h;
        if (lane == 0) {
            g_pm[(bb * NH_ + hh) * NPART_ + sp8] = m[h];
            g_pl[(bb * NH_ + hh) * NPART_ + sp8] = l[h];
        }
        float4 o4 = make_float4(acc[h][0], acc[h][1], acc[h][2], acc[h][3]);
        reinterpret_cast<float4*>(
            &g_po[(((size_t)bb * NH_ + hh) * NPART_ + sp8) * HD_])[lane] = o4;
    }
}

// ---------------- combine 8 partials per (b, head) -------------------------
__global__ void combine_kernel()
{
    const int bh = blockIdx.x;       // b*NH + h
    const int d  = threadIdx.x;      // 128
    float mx = -1e30f;
#pragma unroll
    for (int s = 0; s < NPART_; s++)
        mx = fmaxf(mx, g_pm[bh * NPART_ + s]);
    float lsum = 0.f, osum = 0.f;
#pragma unroll
    for (int s = 0; s < NPART_; s++) {
        float wgt = __expf(g_pm[bh * NPART_ + s] - mx);
        lsum += g_pl[bh * NPART_ + s] * wgt;
        osum += wgt * g_po[((size_t)bh * NPART_ + s) * HD_ + d];
    }
    g_attn[bh * HD_ + d] = osum / lsum;
}

// ---------------- launch ----------------------------------------------------
extern "C" void kernel_launch(void* const* d_in, const int* in_sizes, int n_in,
                              void* d_out, int out_size)
{
    (void)in_sizes; (void)n_in; (void)out_size;
    const float* x  = (const float*)d_in[0];
    const float* wq = (const float*)d_in[1];
    const float* wk = (const float*)d_in[2];
    const float* wv = (const float*)d_in[3];
    const float* wo = (const float*)d_in[4];
    const float* kc = (const float*)d_in[5];
    const float* vc = (const float*)d_in[6];
    const float* fc = (const float*)d_in[7];
    const float* fs = (const float*)d_in[8];
    float* out = (float*)d_out;

    gemm_qkv<<<dim3(48, SK_), 128>>>(x, wq, wk, wv);
    reduce_rope<<<(B_ * 3072) / 256, 256>>>(fc, fs);

    attn_kernel<<<B_ * NKV_ * SPLITS_, 128>>>(kc, vc);
    combine_kernel<<<B_ * NH_, 128>>>();

    gemm_o<<<dim3(32, SK_), 128>>>(wo);
    reduce_wo<<<(B_ * 1024) / 256, 256>>>(out);
}

// round 13
// speedup vs baseline: 1.0363x; 1.0363x over previous
#include <cuda_runtime.h>

#define B_      32
#define DIM_    4096
#define NH_     32
#define NKV_    8
#define HD_     128
#define NREP_   4
#define T_TOT   2048
#define START_  2047
#define QKV_N   6144
#define SK_     8
#define TILE_N  128
#define TILE_K  32
#define SPLITS_ 4
#define TOK_PER_SPLIT 512
#define TOK_PER_WARP  128
#define NPART_  16   // SPLITS_ * 4 warps
#define KT_ROWS 8           // K subtile rows per warp
#define KT_PITCH 132        // floats per row (528B -> conflict-free)
#define NSUB    (TOK_PER_WARP / KT_ROWS)   // 16 subtiles per warp

typedef unsigned long long ull;

// ---------------- scratch (device globals; no runtime allocation) ----------
__device__ float g_part[SK_ * B_ * QKV_N];
__device__ float g_qkv [B_ * QKV_N];
__device__ float g_attn[B_ * NH_ * HD_];
__device__ float g_pm  [B_ * NH_ * NPART_];
__device__ float g_pl  [B_ * NH_ * NPART_];
__device__ float g_po  [(size_t)B_ * NH_ * NPART_ * HD_];

// packed fp32x2 FMA (GEMM only; measured win there)
__device__ __forceinline__ void ffma2(ull& d, ull a, ull b)
{
    asm("fma.rn.f32x2 %0, %1, %2, %0;" : "+l"(d) : "l"(a), "l"(b));
}

// ---------------- split-K tall-skinny GEMM with K-pair FFMA2 ---------------
__device__ __forceinline__ void gemm_body(const float* __restrict__ A,
                                          const float* __restrict__ W,
                                          int N, int col0, int n0, int ky)
{
    __shared__ float xs[B_][TILE_K + 2];
    __shared__ float ws[TILE_N][TILE_K + 2];

    const int kbeg = ky * (DIM_ / SK_);       // 512 per split
    const int tid  = threadIdx.x;
    const int tx   = tid & 15;
    const int ty   = tid >> 4;

    ull acc[4][8];
#pragma unroll
    for (int i = 0; i < 4; i++)
#pragma unroll
        for (int j = 0; j < 8; j++) acc[i][j] = 0ull;

    for (int kt = 0; kt < DIM_ / SK_; kt += TILE_K) {
        const int k0 = kbeg + kt;
#pragma unroll
        for (int it = 0; it < (TILE_K * TILE_N) / 128; it++) {
            int idx = tid + it * 128;
            int kk = idx >> 7;
            int nn = idx & 127;
            ws[nn][kk] = W[(size_t)(k0 + kk) * N + n0 + nn];
        }
#pragma unroll
        for (int it = 0; it < (B_ * TILE_K) / 128; it++) {
            int idx = tid + it * 128;
            int bb = idx >> 5;
            int kk = idx & 31;
            xs[bb][kk] = A[(size_t)bb * DIM_ + k0 + kk];
        }
        __syncthreads();
#pragma unroll
        for (int kp = 0; kp < TILE_K / 2; kp++) {
            ull xv[4], wv[8];
#pragma unroll
            for (int i = 0; i < 4; i++)
                xv[i] = *reinterpret_cast<const ull*>(&xs[ty + 8 * i][2 * kp]);
#pragma unroll
            for (int j = 0; j < 8; j++)
                wv[j] = *reinterpret_cast<const ull*>(&ws[tx + 16 * j][2 * kp]);
#pragma unroll
            for (int i = 0; i < 4; i++)
#pragma unroll
                for (int j = 0; j < 8; j++)
                    ffma2(acc[i][j], xv[i], wv[j]);
        }
        __syncthreads();
    }
#pragma unroll
    for (int i = 0; i < 4; i++) {
        int bb = ty + 8 * i;
#pragma unroll
        for (int j = 0; j < 8; j++) {
            float2 v = *reinterpret_cast<const float2*>(&acc[i][j]);
            int nn = col0 + n0 + tx + 16 * j;
            g_part[((size_t)ky * B_ + bb) * QKV_N + nn] = v.x + v.y;
        }
    }
}

__global__ void __launch_bounds__(128)
gemm_qkv(const float* __restrict__ x, const float* __restrict__ wq,
         const float* __restrict__ wk, const float* __restrict__ wv)
{
    const int tile = blockIdx.x;
    const int ky   = blockIdx.y;
    if (tile < 32)       gemm_body(x, wq, 4096, 0,    tile * TILE_N,        ky);
    else if (tile < 40)  gemm_body(x, wk, 1024, 4096, (tile - 32) * TILE_N, ky);
    else                 gemm_body(x, wv, 1024, 5120, (tile - 40) * TILE_N, ky);
}

__global__ void __launch_bounds__(128)
gemm_o(const float* __restrict__ W)
{
    gemm_body(g_attn, W, 4096, 0, blockIdx.x * TILE_N, blockIdx.y);
}

// ---------------- fused reduce + RoPE (float2 pairs) -----------------------
__global__ void reduce_rope(const float* __restrict__ fc, const float* __restrict__ fs)
{
    const int idx = blockIdx.x * blockDim.x + threadIdx.x;
    const int b2  = idx / 3072;
    const int cp  = idx - b2 * 3072;
    float2 s = make_float2(0.f, 0.f);
#pragma unroll
    for (int ky = 0; ky < SK_; ky++) {
        float2 v = reinterpret_cast<const float2*>(g_part)[(size_t)(ky * B_ + b2) * 3072 + cp];
        s.x += v.x; s.y += v.y;
    }
    if (cp < 2560) {
        int f = cp & 63;
        float c = fc[f], sn = fs[f];
        float xr = s.x, xi = s.y;
        s.x = xr * c - xi * sn;
        s.y = xr * sn + xi * c;
    }
    reinterpret_cast<float2*>(g_qkv)[(size_t)b2 * 3072 + cp] = s;
}

__global__ void reduce_wo(float* __restrict__ out)
{
    const int i = blockIdx.x * blockDim.x + threadIdx.x;
    const int b2 = i >> 10;
    const int nn = i & 1023;
    float4 s = make_float4(0.f, 0.f, 0.f, 0.f);
#pragma unroll
    for (int ky = 0; ky < SK_; ky++) {
        float4 v = reinterpret_cast<const float4*>(g_part)[(size_t)(ky * B_ + b2) * (QKV_N / 4) + nn];
        s.x += v.x; s.y += v.y; s.z += v.z; s.w += v.w;
    }
    reinterpret_cast<float4*>(out)[(size_t)b2 * 1024 + nn] = s;
}

// ---------------- flash-decode attention (K-prefetch pipelined) ------------
// grid: b(32)*g(8)*split(4) = 1024, 128 threads.
// K subtile r+1 is LDG'd while subtile r is scored/softmaxed/V-accumulated;
// the STS at the top of iteration r+1 is the consumer that waits.
__global__ void __launch_bounds__(128)
attn_kernel(const float* __restrict__ kc, const float* __restrict__ vc)
{
    const int blk = blockIdx.x;
    const int sp  = blk & 3;
    const int g   = (blk >> 2) & 7;
    const int bb  = blk >> 5;
    const int tid = threadIdx.x;
    const int w   = tid >> 5;
    const int lane = tid & 31;

    __shared__ float q_s[NREP_][HD_];
    __shared__ float ktile[4][KT_ROWS][KT_PITCH];   // per-warp K subtile

    for (int idx = tid; idx < NREP_ * HD_; idx += 128) {
        int h = idx >> 7, d = idx & 127;
        q_s[h][d] = g_qkv[bb * QKV_N + (g * NREP_ + h) * HD_ + d];
    }
    __syncthreads();

    const float scale = 0.08838834764831845f;   // 1/sqrt(128)
    float m[4], l[4], acc[4][4];
#pragma unroll
    for (int h = 0; h < 4; h++) {
        m[h] = -1e30f; l[h] = 0.f;
#pragma unroll
        for (int j = 0; j < 4; j++) acc[h][j] = 0.f;
    }

    const int tbase = sp * TOK_PER_SPLIT + w * TOK_PER_WARP;
    const float* knew = &g_qkv[bb * QKV_N + 4096 + g * HD_];
    const float* vnew = &g_qkv[bb * QKV_N + 5120 + g * HD_];

    const int tkn = lane & 7;      // token within 8-row subtile
    const int q4i = lane >> 3;     // dim quarter (32 dims each)

    // ---- prologue: prefetch K subtile 0 ----
    float4 kv[KT_ROWS];
#pragma unroll
    for (int rr = 0; rr < KT_ROWS; rr++) {
        const int t = tbase + rr;
        const float* krow = (t == START_)
            ? knew
            : kc + (((size_t)bb * T_TOT + t) * NKV_ + g) * HD_;
        kv[rr] = __ldg(reinterpret_cast<const float4*>(krow) + lane);
    }

    for (int r = 0; r < NSUB; r++) {
        const int tb = tbase + r * KT_ROWS;

        // ---- commit prefetched K to smem (waits on LDGs from prev iter) ----
#pragma unroll
        for (int rr = 0; rr < KT_ROWS; rr++)
            *reinterpret_cast<float4*>(&ktile[w][rr][lane * 4]) = kv[rr];
        __syncwarp();

        // ---- prefetch NEXT K subtile (consumed by STS next iteration) ----
        if (r + 1 < NSUB) {
            const int tb2 = tb + KT_ROWS;
#pragma unroll
            for (int rr = 0; rr < KT_ROWS; rr++) {
                const int t = tb2 + rr;
                const float* krow = (t == START_)
                    ? knew
                    : kc + (((size_t)bb * T_TOT + t) * NKV_ + g) * HD_;
                kv[rr] = __ldg(reinterpret_cast<const float4*>(krow) + lane);
            }
        }

        // ---- scores: 4 lanes per token, 32 dims each ----
        float s4[4] = {0.f, 0.f, 0.f, 0.f};
#pragma unroll
        for (int i = 0; i < 8; i++) {
            float4 k4 = *reinterpret_cast<const float4*>(&ktile[w][tkn][q4i * 32 + i * 4]);
#pragma unroll
            for (int h = 0; h < 4; h++) {
                float4 q4 = *(reinterpret_cast<const float4*>(&q_s[h][q4i * 32]) + i);
                s4[h] += k4.x * q4.x + k4.y * q4.y + k4.z * q4.z + k4.w * q4.w;
            }
        }
        __syncwarp();

        float p[4];
#pragma unroll
        for (int h = 0; h < 4; h++) {
            float sc = s4[h];
            sc += __shfl_xor_sync(0xffffffffu, sc, 8);
            sc += __shfl_xor_sync(0xffffffffu, sc, 16);
            sc *= scale;
            float mx = sc;
#pragma unroll
            for (int o = 4; o > 0; o >>= 1)
                mx = fmaxf(mx, __shfl_xor_sync(0xffffffffu, mx, o));
            float mnew = fmaxf(m[h], mx);
            float corr = __expf(m[h] - mnew);
            p[h] = __expf(sc - mnew);
            float ps = p[h];
#pragma unroll
            for (int o = 4; o > 0; o >>= 1)
                ps += __shfl_xor_sync(0xffffffffu, ps, o);
            l[h] = l[h] * corr + ps;
            m[h] = mnew;
#pragma unroll
            for (int j = 0; j < 4; j++) acc[h][j] *= corr;
        }

        // ---- V accumulation: two batches of 4 rows (16 regs) ----
#pragma unroll
        for (int tt0 = 0; tt0 < KT_ROWS; tt0 += 4) {
            float4 v4b[4];
#pragma unroll
            for (int u = 0; u < 4; u++) {
                const int t2 = tb + tt0 + u;
                const float* vrow = (t2 == START_)
                    ? vnew
                    : vc + (((size_t)bb * T_TOT + t2) * NKV_ + g) * HD_;
                v4b[u] = __ldg(reinterpret_cast<const float4*>(vrow) + lane);
            }
#pragma unroll
            for (int u = 0; u < 4; u++) {
                float pt[4];
#pragma unroll
                for (int h = 0; h < 4; h++)
                    pt[h] = __shfl_sync(0xffffffffu, p[h], tt0 + u);
#pragma unroll
                for (int h = 0; h < 4; h++) {
                    acc[h][0] += pt[h] * v4b[u].x;
                    acc[h][1] += pt[h] * v4b[u].y;
                    acc[h][2] += pt[h] * v4b[u].z;
                    acc[h][3] += pt[h] * v4b[u].w;
                }
            }
        }
    }

    const int sp16 = sp * 4 + w;
#pragma unroll
    for (int h = 0; h < 4; h++) {
        const int hh = g * NREP_ + h;
        if (lane == 0) {
            g_pm[(bb * NH_ + hh) * NPART_ + sp16] = m[h];
            g_pl[(bb * NH_ + hh) * NPART_ + sp16] = l[h];
        }
        float4 o4 = make_float4(acc[h][0], acc[h][1], acc[h][2], acc[h][3]);
        reinterpret_cast<float4*>(
            &g_po[(((size_t)bb * NH_ + hh) * NPART_ + sp16) * HD_])[lane] = o4;
    }
}

// ---------------- combine 16 partials per (b, head) ------------------------
__global__ void combine_kernel()
{
    const int bh = blockIdx.x;       // b*NH + h
    const int d  = threadIdx.x;      // 128
    float mx = -1e30f;
#pragma unroll
    for (int s = 0; s < NPART_; s++)
        mx = fmaxf(mx, g_pm[bh * NPART_ + s]);
    float lsum = 0.f, osum = 0.f;
#pragma unroll
    for (int s = 0; s < NPART_; s++) {
        float wgt = __expf(g_pm[bh * NPART_ + s] - mx);
        lsum += g_pl[bh * NPART_ + s] * wgt;
        osum += wgt * g_po[((size_t)bh * NPART_ + s) * HD_ + d];
    }
    g_attn[bh * HD_ + d] = osum / lsum;
}

// ---------------- launch ----------------------------------------------------
extern "C" void kernel_launch(void* const* d_in, const int* in_sizes, int n_in,
                              void* d_out, int out_size)
{
    (void)in_sizes; (void)n_in; (void)out_size;
    const float* x  = (const float*)d_in[0];
    const float* wq = (const float*)d_in[1];
    const float* wk = (const float*)d_in[2];
    const float* wv = (const float*)d_in[3];
    const float* wo = (const float*)d_in[4];
    const float* kc = (const float*)d_in[5];
    const float* vc = (const float*)d_in[6];
    const float* fc = (const float*)d_in[7];
    const float* fs = (const float*)d_in[8];
    float* out = (float*)d_out;

    gemm_qkv<<<dim3(48, SK_), 128>>>(x, wq, wk, wv);
    reduce_rope<<<(B_ * 3072) / 256, 256>>>(fc, fs);

    attn_kernel<<<B_ * NKV_ * SPLITS_, 128>>>(kc, vc);
    combine_kernel<<<B_ * NH_, 128>>>();

    gemm_o<<<dim3(32, SK_), 128>>>(wo);
    reduce_wo<<<(B_ * 1024) / 256, 256>>>(out);
}

// round 14
// speedup vs baseline: 1.1217x; 1.0824x over previous
#include <cuda_runtime.h>

#define B_      32
#define DIM_    4096
#define NH_     32
#define NKV_    8
#define HD_     128
#define NREP_   4
#define T_TOT   2048
#define START_  2047
#define QKV_N   6144
#define SK_     8
#define TILE_N  128
#define TILE_K  32
#define SPLITS_ 4
#define TOK_PER_SPLIT 512
#define TOK_PER_WARP  128
#define NPART_  16   // SPLITS_ * 4 warps
#define KT_ROWS 8           // K subtile rows per warp
#define KT_PITCH 132        // floats per row (528B -> conflict-free)
#define NSUB    (TOK_PER_WARP / KT_ROWS)   // 16 subtiles per warp

typedef unsigned long long ull;

// ---------------- scratch (device globals; no runtime allocation) ----------
__device__ float g_part[SK_ * B_ * QKV_N];
__device__ float g_qkv [B_ * QKV_N];
__device__ float g_attn[B_ * NH_ * HD_];
__device__ float g_pm  [B_ * NH_ * NPART_];
__device__ float g_pl  [B_ * NH_ * NPART_];
__device__ float g_po  [(size_t)B_ * NH_ * NPART_ * HD_];

// packed fp32x2 FMA (GEMM only; measured win there)
__device__ __forceinline__ void ffma2(ull& d, ull a, ull b)
{
    asm("fma.rn.f32x2 %0, %1, %2, %0;" : "+l"(d) : "l"(a), "l"(b));
}

// ---------------- split-K tall-skinny GEMM with K-pair FFMA2 ---------------
__device__ __forceinline__ void gemm_body(const float* __restrict__ A,
                                          const float* __restrict__ W,
                                          int N, int col0, int n0, int ky)
{
    __shared__ float xs[B_][TILE_K + 2];
    __shared__ float ws[TILE_N][TILE_K + 2];

    const int kbeg = ky * (DIM_ / SK_);       // 512 per split
    const int tid  = threadIdx.x;
    const int tx   = tid & 15;
    const int ty   = tid >> 4;

    ull acc[4][8];
#pragma unroll
    for (int i = 0; i < 4; i++)
#pragma unroll
        for (int j = 0; j < 8; j++) acc[i][j] = 0ull;

    for (int kt = 0; kt < DIM_ / SK_; kt += TILE_K) {
        const int k0 = kbeg + kt;
#pragma unroll
        for (int it = 0; it < (TILE_K * TILE_N) / 128; it++) {
            int idx = tid + it * 128;
            int kk = idx >> 7;
            int nn = idx & 127;
            ws[nn][kk] = W[(size_t)(k0 + kk) * N + n0 + nn];
        }
#pragma unroll
        for (int it = 0; it < (B_ * TILE_K) / 128; it++) {
            int idx = tid + it * 128;
            int bb = idx >> 5;
            int kk = idx & 31;
            xs[bb][kk] = A[(size_t)bb * DIM_ + k0 + kk];
        }
        __syncthreads();
#pragma unroll
        for (int kp = 0; kp < TILE_K / 2; kp++) {
            ull xv[4], wv[8];
#pragma unroll
            for (int i = 0; i < 4; i++)
                xv[i] = *reinterpret_cast<const ull*>(&xs[ty + 8 * i][2 * kp]);
#pragma unroll
            for (int j = 0; j < 8; j++)
                wv[j] = *reinterpret_cast<const ull*>(&ws[tx + 16 * j][2 * kp]);
#pragma unroll
            for (int i = 0; i < 4; i++)
#pragma unroll
                for (int j = 0; j < 8; j++)
                    ffma2(acc[i][j], xv[i], wv[j]);
        }
        __syncthreads();
    }
#pragma unroll
    for (int i = 0; i < 4; i++) {
        int bb = ty + 8 * i;
#pragma unroll
        for (int j = 0; j < 8; j++) {
            float2 v = *reinterpret_cast<const float2*>(&acc[i][j]);
            int nn = col0 + n0 + tx + 16 * j;
            g_part[((size_t)ky * B_ + bb) * QKV_N + nn] = v.x + v.y;
        }
    }
}

__global__ void __launch_bounds__(128)
gemm_qkv(const float* __restrict__ x, const float* __restrict__ wq,
         const float* __restrict__ wk, const float* __restrict__ wv)
{
    const int tile = blockIdx.x;
    const int ky   = blockIdx.y;
    if (tile < 32)       gemm_body(x, wq, 4096, 0,    tile * TILE_N,        ky);
    else if (tile < 40)  gemm_body(x, wk, 1024, 4096, (tile - 32) * TILE_N, ky);
    else                 gemm_body(x, wv, 1024, 5120, (tile - 40) * TILE_N, ky);
}

__global__ void __launch_bounds__(128)
gemm_o(const float* __restrict__ W)
{
    gemm_body(g_attn, W, 4096, 0, blockIdx.x * TILE_N, blockIdx.y);
}

// ---------------- fused reduce + RoPE (float2 pairs) -----------------------
__global__ void reduce_rope(const float* __restrict__ fc, const float* __restrict__ fs)
{
    const int idx = blockIdx.x * blockDim.x + threadIdx.x;
    const int b2  = idx / 3072;
    const int cp  = idx - b2 * 3072;
    float2 s = make_float2(0.f, 0.f);
#pragma unroll
    for (int ky = 0; ky < SK_; ky++) {
        float2 v = reinterpret_cast<const float2*>(g_part)[(size_t)(ky * B_ + b2) * 3072 + cp];
        s.x += v.x; s.y += v.y;
    }
    if (cp < 2560) {
        int f = cp & 63;
        float c = fc[f], sn = fs[f];
        float xr = s.x, xi = s.y;
        s.x = xr * c - xi * sn;
        s.y = xr * sn + xi * c;
    }
    reinterpret_cast<float2*>(g_qkv)[(size_t)b2 * 3072 + cp] = s;
}

__global__ void reduce_wo(float* __restrict__ out)
{
    const int i = blockIdx.x * blockDim.x + threadIdx.x;
    const int b2 = i >> 10;
    const int nn = i & 1023;
    float4 s = make_float4(0.f, 0.f, 0.f, 0.f);
#pragma unroll
    for (int ky = 0; ky < SK_; ky++) {
        float4 v = reinterpret_cast<const float4*>(g_part)[(size_t)(ky * B_ + b2) * (QKV_N / 4) + nn];
        s.x += v.x; s.y += v.y; s.z += v.z; s.w += v.w;
    }
    reinterpret_cast<float4*>(out)[(size_t)b2 * 1024 + nn] = s;
}

// ---------------- flash-decode attention: exact two-pass softmax -----------
// grid: b(32)*g(8)*split(4) = 1024 blocks, 128 threads.
// Phase 1: stream K, raw scores -> smem (per-lane running max, no trees).
// Phase 2: one max/sum reduction pass, exp in place.
// Phase 3: stream V, p via LDS.128 broadcast, no rescaling.
__global__ void __launch_bounds__(128)
attn_kernel(const float* __restrict__ kc, const float* __restrict__ vc)
{
    const int blk = blockIdx.x;
    const int sp  = blk & 3;
    const int g   = (blk >> 2) & 7;
    const int bb  = blk >> 5;
    const int tid = threadIdx.x;
    const int w   = tid >> 5;
    const int lane = tid & 31;

    __shared__ float q_s[NREP_][HD_];
    __shared__ float ktile[4][KT_ROWS][KT_PITCH];   // per-warp K subtile
    __shared__ float4 s_p[4][TOK_PER_WARP];         // per-warp scores/probs [token]{h0..h3}

    for (int idx = tid; idx < NREP_ * HD_; idx += 128) {
        int h = idx >> 7, d = idx & 127;
        q_s[h][d] = g_qkv[bb * QKV_N + (g * NREP_ + h) * HD_ + d];
    }
    __syncthreads();

    const float scale = 0.08838834764831845f;   // 1/sqrt(128)
    const int tbase = sp * TOK_PER_SPLIT + w * TOK_PER_WARP;
    const float* knew = &g_qkv[bb * QKV_N + 4096 + g * HD_];
    const float* vnew = &g_qkv[bb * QKV_N + 5120 + g * HD_];

    const int tkn = lane & 7;      // token within 8-row subtile
    const int q4i = lane >> 3;     // dim quarter (32 dims each)

    float m[4];
#pragma unroll
    for (int h = 0; h < 4; h++) m[h] = -1e30f;

    // ================= Phase 1: K pass, raw scores to smem =================
    for (int r = 0; r < NSUB; r++) {
        const int tb = tbase + r * KT_ROWS;

        // coalesced K fill: one 512B row per iteration
#pragma unroll
        for (int rr = 0; rr < KT_ROWS; rr++) {
            const int t = tb + rr;
            const float* krow = (t == START_)
                ? knew
                : kc + (((size_t)bb * T_TOT + t) * NKV_ + g) * HD_;
            float4 kv = __ldg(reinterpret_cast<const float4*>(krow) + lane);
            *reinterpret_cast<float4*>(&ktile[w][rr][lane * 4]) = kv;
        }
        __syncwarp();

        // scores: 4 lanes per token, 32 dims each
        float s4[4] = {0.f, 0.f, 0.f, 0.f};
#pragma unroll
        for (int i = 0; i < 8; i++) {
            float4 k4 = *reinterpret_cast<const float4*>(&ktile[w][tkn][q4i * 32 + i * 4]);
#pragma unroll
            for (int h = 0; h < 4; h++) {
                float4 q4 = *(reinterpret_cast<const float4*>(&q_s[h][q4i * 32]) + i);
                s4[h] += k4.x * q4.x + k4.y * q4.y + k4.z * q4.z + k4.w * q4.w;
            }
        }
        __syncwarp();

        // merge dim quarters (lane bits 3,4); all lanes end with token tkn's score
#pragma unroll
        for (int h = 0; h < 4; h++) {
            float sc = s4[h];
            sc += __shfl_xor_sync(0xffffffffu, sc, 8);
            sc += __shfl_xor_sync(0xffffffffu, sc, 16);
            sc *= scale;
            s4[h] = sc;
            m[h] = fmaxf(m[h], sc);
        }
        // one writer per token (q4i==0 lanes), all 4 heads in one STS.128
        if (q4i == 0)
            s_p[w][r * KT_ROWS + tkn] = make_float4(s4[0], s4[1], s4[2], s4[3]);
    }
    __syncwarp();

    // ================= Phase 2: finalize softmax =================
    // per-lane m[h] covers tokens == tkn (mod 8); reduce over tkn bits 0..2
#pragma unroll
    for (int h = 0; h < 4; h++) {
#pragma unroll
        for (int o = 4; o > 0; o >>= 1)
            m[h] = fmaxf(m[h], __shfl_xor_sync(0xffffffffu, m[h], o));
    }
    float l[4] = {0.f, 0.f, 0.f, 0.f};
#pragma unroll
    for (int i = 0; i < TOK_PER_WARP / 32; i++) {
        const int t = lane + 32 * i;
        float4 sv = s_p[w][t];
        float4 ev;
        ev.x = __expf(sv.x - m[0]);
        ev.y = __expf(sv.y - m[1]);
        ev.z = __expf(sv.z - m[2]);
        ev.w = __expf(sv.w - m[3]);
        l[0] += ev.x; l[1] += ev.y; l[2] += ev.z; l[3] += ev.w;
        s_p[w][t] = ev;
    }
    __syncwarp();
#pragma unroll
    for (int h = 0; h < 4; h++) {
#pragma unroll
        for (int o = 16; o > 0; o >>= 1)
            l[h] += __shfl_xor_sync(0xffffffffu, l[h], o);
    }

    // ================= Phase 3: V pass =================
    float acc[4][4];
#pragma unroll
    for (int h = 0; h < 4; h++)
#pragma unroll
        for (int j = 0; j < 4; j++) acc[h][j] = 0.f;

    for (int r = 0; r < NSUB; r++) {
        const int tb = tbase + r * KT_ROWS;
        float4 v8[KT_ROWS];
#pragma unroll
        for (int u = 0; u < KT_ROWS; u++) {
            const int t2 = tb + u;
            const float* vrow = (t2 == START_)
                ? vnew
                : vc + (((size_t)bb * T_TOT + t2) * NKV_ + g) * HD_;
            v8[u] = __ldg(reinterpret_cast<const float4*>(vrow) + lane);
        }
#pragma unroll
        for (int u = 0; u < KT_ROWS; u++) {
            float4 p4 = s_p[w][r * KT_ROWS + u];    // LDS.128 broadcast
            float pt[4] = {p4.x, p4.y, p4.z, p4.w};
#pragma unroll
            for (int h = 0; h < 4; h++) {
                acc[h][0] += pt[h] * v8[u].x;
                acc[h][1] += pt[h] * v8[u].y;
                acc[h][2] += pt[h] * v8[u].z;
                acc[h][3] += pt[h] * v8[u].w;
            }
        }
    }

    const int sp16 = sp * 4 + w;
#pragma unroll
    for (int h = 0; h < 4; h++) {
        const int hh = g * NREP_ + h;
        if (lane == 0) {
            g_pm[(bb * NH_ + hh) * NPART_ + sp16] = m[h];
            g_pl[(bb * NH_ + hh) * NPART_ + sp16] = l[h];
        }
        float4 o4 = make_float4(acc[h][0], acc[h][1], acc[h][2], acc[h][3]);
        reinterpret_cast<float4*>(
            &g_po[(((size_t)bb * NH_ + hh) * NPART_ + sp16) * HD_])[lane] = o4;
    }
}

// ---------------- combine 16 partials per (b, head) ------------------------
__global__ void combine_kernel()
{
    const int bh = blockIdx.x;       // b*NH + h
    const int d  = threadIdx.x;      // 128
    float mx = -1e30f;
#pragma unroll
    for (int s = 0; s < NPART_; s++)
        mx = fmaxf(mx, g_pm[bh * NPART_ + s]);
    float lsum = 0.f, osum = 0.f;
#pragma unroll
    for (int s = 0; s < NPART_; s++) {
        float wgt = __expf(g_pm[bh * NPART_ + s] - mx);
        lsum += g_pl[bh * NPART_ + s] * wgt;
        osum += wgt * g_po[((size_t)bh * NPART_ + s) * HD_ + d];
    }
    g_attn[bh * HD_ + d] = osum / lsum;
}

// ---------------- launch ----------------------------------------------------
extern "C" void kernel_launch(void* const* d_in, const int* in_sizes, int n_in,
                              void* d_out, int out_size)
{
    (void)in_sizes; (void)n_in; (void)out_size;
    const float* x  = (const float*)d_in[0];
    const float* wq = (const float*)d_in[1];
    const float* wk = (const float*)d_in[2];
    const float* wv = (const float*)d_in[3];
    const float* wo = (const float*)d_in[4];
    const float* kc = (const float*)d_in[5];
    const float* vc = (const float*)d_in[6];
    const float* fc = (const float*)d_in[7];
    const float* fs = (const float*)d_in[8];
    float* out = (float*)d_out;

    gemm_qkv<<<dim3(48, SK_), 128>>>(x, wq, wk, wv);
    reduce_rope<<<(B_ * 3072) / 256, 256>>>(fc, fs);

    attn_kernel<<<B_ * NKV_ * SPLITS_, 128>>>(kc, vc);
    combine_kernel<<<B_ * NH_, 128>>>();

    gemm_o<<<dim3(32, SK_), 128>>>(wo);
    reduce_wo<<<(B_ * 1024) / 256, 256>>>(out);
}